// round 1
// baseline (speedup 1.0000x reference)
#include <cuda_runtime.h>

// Problem constants
#define CC      128
#define GROUPS  8
#define NB      4
#define NN      8192
#define MM      32768
#define KNN     16
#define NROWS   (NB*NN)              // 32768 rows total
#define ROWS_PER_BLK 64
#define THREADS 256
#define CNT_INV (1.0f/131072.0f)     // 1/(N * C/G) = 1/(8192*16)
#define SMEM_BYTES ((ROWS_PER_BLK*CC + CC*CC)*4)   // xs + wt = 98304 B

// Scratch (device globals; no cudaMalloc allowed)
__device__ float g_Wt[3][CC*CC];          // transposed weights  Wt[c][k] = W[k][c]
__device__ float g_sum[3][NB*GROUPS];     // per-layer group sums
__device__ float g_sqs[3][NB*GROUPS];     // per-layer group sum-of-squares
__device__ float g_buf0[NROWS*CC];
__device__ float g_buf1[NROWS*CC];

// packed f32x2 FMA (sm_100+): d = a*b + c elementwise on 2 packed floats
__device__ __forceinline__ unsigned long long ffma2(unsigned long long a,
                                                    unsigned long long b,
                                                    unsigned long long c) {
    unsigned long long d;
    asm("fma.rn.f32x2 %0, %1, %2, %3;" : "=l"(d) : "l"(a), "l"(b), "l"(c));
    return d;
}
__device__ __forceinline__ float f2lo(unsigned long long v) {
    return __uint_as_float((unsigned)(v & 0xffffffffULL));
}
__device__ __forceinline__ float f2hi(unsigned long long v) {
    return __uint_as_float((unsigned)(v >> 32));
}
__device__ __forceinline__ float leaky(float h) { return h >= 0.0f ? h : 0.1f * h; }

// ---------------------------------------------------------------------------
// Prep: zero the stats accumulators, transpose W1/W2/W3 into g_Wt
// ---------------------------------------------------------------------------
__global__ void prep_kernel(const float* __restrict__ W1,
                            const float* __restrict__ W2,
                            const float* __restrict__ W3) {
    int idx = blockIdx.x * THREADS + threadIdx.x;
    if (blockIdx.x == 0) {
        int t = threadIdx.x;
        if (t < 96)        { g_sum[t / 32][t % 32] = 0.0f; }
        else if (t < 192)  { int u = t - 96; g_sqs[u / 32][u % 32] = 0.0f; }
    }
    if (idx < 3 * CC * CC) {
        int l = idx / (CC * CC);
        int r = idx % (CC * CC);
        int k = r % CC;              // fast dim -> coalesced store
        int c = r / CC;
        const float* W = (l == 0) ? W1 : ((l == 1) ? W2 : W3);
        g_Wt[l][c * CC + k] = W[k * CC + c];
    }
}

// ---------------------------------------------------------------------------
// Fused layer kernel.
// MODE 0: input = IDW-weighted KNN gather (layer 1)
// MODE 1: input = leaky(GN(prev_y))                      (layer 2)
// MODE 2: input = leaky(GN(prev_y)) + resid (q_feats)    (layer 3)
// Computes y = input @ W[layer] + b[layer]  (pre-GN), writes to out_y,
// and atomically accumulates per-(batch,group) sum / sumsq into g_sum/g_sqs.
// ---------------------------------------------------------------------------
template <int MODE>
__global__ __launch_bounds__(THREADS, 2)
void layer_kernel(const float* __restrict__ in_y,
                  const float* __restrict__ resid,
                  const float* __restrict__ s_feats,
                  const float* __restrict__ q_points,
                  const float* __restrict__ s_points,
                  const int*   __restrict__ nbr_idx,
                  const float* __restrict__ bias,
                  const float* __restrict__ gamma_prev,
                  const float* __restrict__ beta_prev,
                  int layer,
                  float* __restrict__ out_y) {
    extern __shared__ float smem[];
    float* xs = smem;                        // [64][128] input tile
    float* wt = smem + ROWS_PER_BLK * CC;    // [128][128] Wt (c-major, k-contig)
    __shared__ float s_ms[GROUPS], s_rs[GROUPS];
    __shared__ float s_gb[2 * CC];
    __shared__ float s_gsum[GROUPS], s_gsqs[GROUPS];

    const int tid  = threadIdx.x;
    const int wid  = tid >> 5;
    const int lane = tid & 31;
    const int row0 = blockIdx.x * ROWS_PER_BLK;  // 64 rows, all one batch
    const int b    = row0 >> 13;                  // /8192

    // Stage W^T into shared (coalesced, conflict-free)
    const float* Wt = g_Wt[layer];
    #pragma unroll
    for (int i = 0; i < (CC * CC) / THREADS; i++)
        wt[tid + i * THREADS] = Wt[tid + i * THREADS];

    if (tid < GROUPS) { s_gsum[tid] = 0.0f; s_gsqs[tid] = 0.0f; }

    // ---- Stage 1: build xs[64][128] ----
    if (MODE == 0) {
        // one warp per 8 rows; lane owns cols 4*lane..4*lane+3 (float4)
        for (int rr = 0; rr < 8; rr++) {
            int r    = wid * 8 + rr;
            int grow = row0 + r;
            int n    = grow & (NN - 1);
            int base = b * NN + n;
            float qx = q_points[base * 3 + 0];
            float qy = q_points[base * 3 + 1];
            float qz = q_points[base * 3 + 2];
            float wk[KNN];
            float wsum = 0.0f;
            #pragma unroll
            for (int k = 0; k < KNN; k++) {
                const float* sp = s_points + (base * KNN + k) * 3;
                float dx = sp[0] - qx, dy = sp[1] - qy, dz = sp[2] - qz;
                float d2 = dx * dx + dy * dy + dz * dz;
                wk[k] = 1.0f / (d2 + 1e-8f);
                wsum += wk[k];
            }
            float4 acc = make_float4(0.f, 0.f, 0.f, 0.f);
            #pragma unroll
            for (int k = 0; k < KNN; k++) {
                int id = nbr_idx[base * KNN + k];
                const float4* fr = (const float4*)(s_feats + (b * MM + id) * CC);
                float4 v = fr[lane];
                acc.x += wk[k] * v.x; acc.y += wk[k] * v.y;
                acc.z += wk[k] * v.z; acc.w += wk[k] * v.w;
            }
            float inv = 1.0f / wsum;
            acc.x *= inv; acc.y *= inv; acc.z *= inv; acc.w *= inv;
            *(float4*)&xs[r * CC + lane * 4] = acc;
        }
    } else {
        // finalize previous layer's GroupNorm stats
        if (tid < GROUPS) {
            float s  = g_sum[layer - 1][b * GROUPS + tid];
            float s2 = g_sqs[layer - 1][b * GROUPS + tid];
            float m  = s * CNT_INV;
            float v  = s2 * CNT_INV - m * m;
            s_ms[tid] = m;
            s_rs[tid] = rsqrtf(v + 1e-5f);
        }
        if (tid < CC) { s_gb[tid] = gamma_prev[tid]; s_gb[CC + tid] = beta_prev[tid]; }
        __syncthreads();
        #pragma unroll
        for (int i = 0; i < 8; i++) {
            int f  = tid + i * THREADS;        // float4 index within tile (2048)
            int r  = f >> 5;                   // 32 float4 per row
            int c4 = (f & 31) * 4;
            int g  = c4 >> 4;
            float m = s_ms[g], rs = s_rs[g];
            float4 v = *(const float4*)&in_y[(row0 + r) * CC + c4];
            float4 o;
            o.x = leaky((v.x - m) * rs * s_gb[c4 + 0] + s_gb[CC + c4 + 0]);
            o.y = leaky((v.y - m) * rs * s_gb[c4 + 1] + s_gb[CC + c4 + 1]);
            o.z = leaky((v.z - m) * rs * s_gb[c4 + 2] + s_gb[CC + c4 + 2]);
            o.w = leaky((v.w - m) * rs * s_gb[c4 + 3] + s_gb[CC + c4 + 3]);
            if (MODE == 2) {
                float4 q = *(const float4*)&resid[(row0 + r) * CC + c4];
                o.x += q.x; o.y += q.y; o.z += q.z; o.w += q.w;
            }
            *(float4*)&xs[r * CC + c4] = o;
        }
    }
    __syncthreads();

    // ---- Stage 2: GEMM. Thread micro-tile: rows wid*8..+7, cols lane+32j.
    // f32x2 accumulators hold (even-k, odd-k) partial sums.
    unsigned long long acc[8][4];
    #pragma unroll
    for (int i = 0; i < 8; i++)
        #pragma unroll
        for (int j = 0; j < 4; j++) acc[i][j] = 0ULL;

    const float* xrow = xs + wid * 8 * CC;
    #pragma unroll 4
    for (int kq = 0; kq < CC / 4; kq++) {
        int k0 = kq * 4;
        ulonglong2 xv[8];
        #pragma unroll
        for (int i = 0; i < 8; i++)
            xv[i] = *(const ulonglong2*)(xrow + i * CC + k0);
        #pragma unroll
        for (int j = 0; j < 4; j++) {
            ulonglong2 wv = *(const ulonglong2*)(wt + (lane + 32 * j) * CC + k0);
            #pragma unroll
            for (int i = 0; i < 8; i++) {
                acc[i][j] = ffma2(xv[i].x, wv.x, acc[i][j]);
                acc[i][j] = ffma2(xv[i].y, wv.y, acc[i][j]);
            }
        }
    }

    // ---- Epilogue: bias, write y, accumulate group stats ----
    float bj[4];
    #pragma unroll
    for (int j = 0; j < 4; j++) bj[j] = bias[lane + 32 * j];

    #pragma unroll
    for (int j = 0; j < 4; j++) {
        int   c = lane + 32 * j;
        int   g = (lane >> 4) + 2 * j;
        float s = 0.0f, s2 = 0.0f;
        #pragma unroll
        for (int i = 0; i < 8; i++) {
            float y = f2lo(acc[i][j]) + f2hi(acc[i][j]) + bj[j];
            out_y[(row0 + wid * 8 + i) * CC + c] = y;
            s  += y;
            s2 += y * y;
        }
        atomicAdd(&s_gsum[g], s);
        atomicAdd(&s_gsqs[g], s2);
    }
    __syncthreads();
    if (tid < GROUPS) {
        atomicAdd(&g_sum[layer][b * GROUPS + tid], s_gsum[tid]);
        atomicAdd(&g_sqs[layer][b * GROUPS + tid], s_gsqs[tid]);
    }
}

// ---------------------------------------------------------------------------
// Finalize: out = leaky(GN3(y3))
// ---------------------------------------------------------------------------
__global__ void finalize_kernel(const float* __restrict__ in_y,
                                const float* __restrict__ gamma,
                                const float* __restrict__ beta,
                                float* __restrict__ out) {
    int f  = blockIdx.x * blockDim.x + threadIdx.x;   // float4 index
    int e  = f * 4;
    int c4 = e & (CC - 1);
    int row = e >> 7;
    int b  = row >> 13;
    int g  = c4 >> 4;
    float s  = g_sum[2][b * GROUPS + g];
    float s2 = g_sqs[2][b * GROUPS + g];
    float m  = s * CNT_INV;
    float v  = s2 * CNT_INV - m * m;
    float rs = rsqrtf(v + 1e-5f);
    float4 x = *(const float4*)&in_y[e];
    float4 o;
    o.x = leaky((x.x - m) * rs * gamma[c4 + 0] + beta[c4 + 0]);
    o.y = leaky((x.y - m) * rs * gamma[c4 + 1] + beta[c4 + 1]);
    o.z = leaky((x.z - m) * rs * gamma[c4 + 2] + beta[c4 + 2]);
    o.w = leaky((x.w - m) * rs * gamma[c4 + 3] + beta[c4 + 3]);
    *(float4*)&out[e] = o;
}

// ---------------------------------------------------------------------------
extern "C" void kernel_launch(void* const* d_in, const int* in_sizes, int n_in,
                              void* d_out, int out_size) {
    const float* q_feats  = (const float*)d_in[0];
    const float* s_feats  = (const float*)d_in[1];
    const float* q_points = (const float*)d_in[2];
    const float* s_points = (const float*)d_in[3];
    const int*   nbr_idx  = (const int*)  d_in[4];
    const float* W1 = (const float*)d_in[5];
    const float* b1 = (const float*)d_in[6];
    const float* g1 = (const float*)d_in[7];
    const float* be1 = (const float*)d_in[8];
    const float* W2 = (const float*)d_in[9];
    const float* b2 = (const float*)d_in[10];
    const float* g2 = (const float*)d_in[11];
    const float* be2 = (const float*)d_in[12];
    const float* W3 = (const float*)d_in[13];
    const float* b3 = (const float*)d_in[14];
    const float* g3 = (const float*)d_in[15];
    const float* be3 = (const float*)d_in[16];
    float* out = (float*)d_out;

    float *buf0 = nullptr, *buf1 = nullptr;
    cudaGetSymbolAddress((void**)&buf0, g_buf0);
    cudaGetSymbolAddress((void**)&buf1, g_buf1);

    cudaFuncSetAttribute(layer_kernel<0>, cudaFuncAttributeMaxDynamicSharedMemorySize, SMEM_BYTES);
    cudaFuncSetAttribute(layer_kernel<1>, cudaFuncAttributeMaxDynamicSharedMemorySize, SMEM_BYTES);
    cudaFuncSetAttribute(layer_kernel<2>, cudaFuncAttributeMaxDynamicSharedMemorySize, SMEM_BYTES);

    prep_kernel<<<(3 * CC * CC + THREADS - 1) / THREADS, THREADS>>>(W1, W2, W3);

    const int nblk = NROWS / ROWS_PER_BLK;   // 512
    layer_kernel<0><<<nblk, THREADS, SMEM_BYTES>>>(
        nullptr, nullptr, s_feats, q_points, s_points, nbr_idx,
        b1, nullptr, nullptr, 0, buf0);
    layer_kernel<1><<<nblk, THREADS, SMEM_BYTES>>>(
        buf0, nullptr, nullptr, nullptr, nullptr, nullptr,
        b2, g1, be1, 1, buf1);
    layer_kernel<2><<<nblk, THREADS, SMEM_BYTES>>>(
        buf1, q_feats, nullptr, nullptr, nullptr, nullptr,
        b3, g2, be2, 2, buf0);
    finalize_kernel<<<(NROWS * CC / 4) / THREADS, THREADS>>>(buf0, g3, be3, out);
}

// round 2
// speedup vs baseline: 1.4928x; 1.4928x over previous
#include <cuda_runtime.h>

// Problem constants
#define CC      128
#define CCP     132                  // padded W^T row stride (floats) -> conflict-free LDS.128
#define GROUPS  8
#define NB      4
#define NN      8192
#define MM      32768
#define KNN     16
#define NROWS   (NB*NN)              // 32768 rows total
#define ROWS_PER_BLK 64
#define THREADS 256
#define CNT_INV (1.0f/131072.0f)     // 1/(N * C/G) = 1/(8192*16)
#define SMEM_BYTES ((ROWS_PER_BLK*CC + CC*CCP)*4)   // xs + wt = 100352 B

// Scratch (device globals; no cudaMalloc allowed)
__device__ float g_Wt[3][CC*CC];          // transposed weights  Wt[c][k] = W[k][c]
__device__ float g_sum[3][NB*GROUPS];     // per-layer group sums
__device__ float g_sqs[3][NB*GROUPS];     // per-layer group sum-of-squares
__device__ float g_buf0[NROWS*CC];
__device__ float g_buf1[NROWS*CC];

// packed f32x2 FMA (sm_100+): d = a*b + c elementwise on 2 packed floats
__device__ __forceinline__ unsigned long long ffma2(unsigned long long a,
                                                    unsigned long long b,
                                                    unsigned long long c) {
    unsigned long long d;
    asm("fma.rn.f32x2 %0, %1, %2, %3;" : "=l"(d) : "l"(a), "l"(b), "l"(c));
    return d;
}
__device__ __forceinline__ float f2lo(unsigned long long v) {
    return __uint_as_float((unsigned)(v & 0xffffffffULL));
}
__device__ __forceinline__ float f2hi(unsigned long long v) {
    return __uint_as_float((unsigned)(v >> 32));
}
__device__ __forceinline__ float leaky(float h) { return h >= 0.0f ? h : 0.1f * h; }

// ---------------------------------------------------------------------------
// Prep: zero the stats accumulators, transpose W1/W2/W3 into g_Wt
// ---------------------------------------------------------------------------
__global__ void prep_kernel(const float* __restrict__ W1,
                            const float* __restrict__ W2,
                            const float* __restrict__ W3) {
    int idx = blockIdx.x * THREADS + threadIdx.x;
    if (blockIdx.x == 0) {
        int t = threadIdx.x;
        if (t < 96)        { g_sum[t / 32][t % 32] = 0.0f; }
        else if (t < 192)  { int u = t - 96; g_sqs[u / 32][u % 32] = 0.0f; }
    }
    if (idx < 3 * CC * CC) {
        int l = idx / (CC * CC);
        int r = idx % (CC * CC);
        int k = r % CC;              // fast dim -> coalesced store
        int c = r / CC;
        const float* W = (l == 0) ? W1 : ((l == 1) ? W2 : W3);
        g_Wt[l][c * CC + k] = W[k * CC + c];
    }
}

// ---------------------------------------------------------------------------
// Fused layer kernel.
// MODE 0: input = IDW-weighted KNN gather (layer 1)
// MODE 1: input = leaky(GN(prev_y))                      (layer 2)
// MODE 2: input = leaky(GN(prev_y)) + resid (q_feats)    (layer 3)
// Computes y = input @ W[layer] + b[layer]  (pre-GN), writes to out_y,
// and atomically accumulates per-(batch,group) sum / sumsq into g_sum/g_sqs.
// ---------------------------------------------------------------------------
template <int MODE>
__global__ __launch_bounds__(THREADS, 2)
void layer_kernel(const float* __restrict__ in_y,
                  const float* __restrict__ resid,
                  const float* __restrict__ s_feats,
                  const float* __restrict__ q_points,
                  const float* __restrict__ s_points,
                  const int*   __restrict__ nbr_idx,
                  const float* __restrict__ bias,
                  const float* __restrict__ gamma_prev,
                  const float* __restrict__ beta_prev,
                  int layer,
                  float* __restrict__ out_y) {
    extern __shared__ float smem[];
    float* xs = smem;                        // [64][128] input tile
    float* wt = smem + ROWS_PER_BLK * CC;    // [128][CCP] Wt (c-major, k-contig, padded)
    __shared__ float s_ms[GROUPS], s_rs[GROUPS];
    __shared__ float s_gb[2 * CC];
    __shared__ float s_gsum[GROUPS], s_gsqs[GROUPS];

    const int tid  = threadIdx.x;
    const int wid  = tid >> 5;
    const int lane = tid & 31;
    const int row0 = blockIdx.x * ROWS_PER_BLK;  // 64 rows, all one batch
    const int b    = row0 >> 13;                  // /8192

    // Stage W^T into shared (coalesced reads; padded row stride in smem)
    const float* Wt = g_Wt[layer];
    #pragma unroll
    for (int i = 0; i < (CC * CC) / THREADS; i++) {
        int idx = tid + i * THREADS;
        int c = idx >> 7;            // /CC
        int k = idx & (CC - 1);
        wt[c * CCP + k] = Wt[idx];
    }

    if (tid < GROUPS) { s_gsum[tid] = 0.0f; s_gsqs[tid] = 0.0f; }

    // ---- Stage 1: build xs[64][128] ----
    if (MODE == 0) {
        // one warp per 8 rows; lane owns cols 4*lane..4*lane+3 (float4)
        for (int rr = 0; rr < 8; rr++) {
            int r    = wid * 8 + rr;
            int grow = row0 + r;
            int n    = grow & (NN - 1);
            int base = b * NN + n;
            float qx = q_points[base * 3 + 0];
            float qy = q_points[base * 3 + 1];
            float qz = q_points[base * 3 + 2];
            float wk[KNN];
            float wsum = 0.0f;
            #pragma unroll
            for (int k = 0; k < KNN; k++) {
                const float* sp = s_points + (base * KNN + k) * 3;
                float dx = sp[0] - qx, dy = sp[1] - qy, dz = sp[2] - qz;
                float d2 = dx * dx + dy * dy + dz * dz;
                wk[k] = 1.0f / (d2 + 1e-8f);
                wsum += wk[k];
            }
            float4 acc = make_float4(0.f, 0.f, 0.f, 0.f);
            #pragma unroll
            for (int k = 0; k < KNN; k++) {
                int id = nbr_idx[base * KNN + k];
                const float4* fr = (const float4*)(s_feats + (b * MM + id) * CC);
                float4 v = fr[lane];
                acc.x += wk[k] * v.x; acc.y += wk[k] * v.y;
                acc.z += wk[k] * v.z; acc.w += wk[k] * v.w;
            }
            float inv = 1.0f / wsum;
            acc.x *= inv; acc.y *= inv; acc.z *= inv; acc.w *= inv;
            *(float4*)&xs[r * CC + lane * 4] = acc;
        }
    } else {
        // finalize previous layer's GroupNorm stats
        if (tid < GROUPS) {
            float s  = g_sum[layer - 1][b * GROUPS + tid];
            float s2 = g_sqs[layer - 1][b * GROUPS + tid];
            float m  = s * CNT_INV;
            float v  = s2 * CNT_INV - m * m;
            s_ms[tid] = m;
            s_rs[tid] = rsqrtf(v + 1e-5f);
        }
        if (tid < CC) { s_gb[tid] = gamma_prev[tid]; s_gb[CC + tid] = beta_prev[tid]; }
        __syncthreads();
        #pragma unroll
        for (int i = 0; i < 8; i++) {
            int f  = tid + i * THREADS;        // float4 index within tile (2048)
            int r  = f >> 5;                   // 32 float4 per row
            int c4 = (f & 31) * 4;
            int g  = c4 >> 4;
            float m = s_ms[g], rs = s_rs[g];
            float4 v = *(const float4*)&in_y[(row0 + r) * CC + c4];
            float4 o;
            o.x = leaky((v.x - m) * rs * s_gb[c4 + 0] + s_gb[CC + c4 + 0]);
            o.y = leaky((v.y - m) * rs * s_gb[c4 + 1] + s_gb[CC + c4 + 1]);
            o.z = leaky((v.z - m) * rs * s_gb[c4 + 2] + s_gb[CC + c4 + 2]);
            o.w = leaky((v.w - m) * rs * s_gb[c4 + 3] + s_gb[CC + c4 + 3]);
            if (MODE == 2) {
                float4 q = *(const float4*)&resid[(row0 + r) * CC + c4];
                o.x += q.x; o.y += q.y; o.z += q.z; o.w += q.w;
            }
            *(float4*)&xs[r * CC + c4] = o;
        }
    }
    __syncthreads();

    // ---- Stage 2: GEMM. Thread micro-tile: rows wid*8..+7, cols lane+32j.
    // f32x2 accumulators hold (even-k, odd-k) partial sums.
    unsigned long long acc[8][4];
    #pragma unroll
    for (int i = 0; i < 8; i++)
        #pragma unroll
        for (int j = 0; j < 4; j++) acc[i][j] = 0ULL;

    const float* xrow = xs + wid * 8 * CC;
    const float* wlane = wt + lane * CCP;
    #pragma unroll 4
    for (int kq = 0; kq < CC / 4; kq++) {
        int k0 = kq * 4;
        ulonglong2 xv[8];
        #pragma unroll
        for (int i = 0; i < 8; i++)
            xv[i] = *(const ulonglong2*)(xrow + i * CC + k0);
        #pragma unroll
        for (int j = 0; j < 4; j++) {
            ulonglong2 wv = *(const ulonglong2*)(wlane + (32 * j) * CCP + k0);
            #pragma unroll
            for (int i = 0; i < 8; i++) {
                acc[i][j] = ffma2(xv[i].x, wv.x, acc[i][j]);
                acc[i][j] = ffma2(xv[i].y, wv.y, acc[i][j]);
            }
        }
    }

    // ---- Epilogue: bias, write y, accumulate group stats ----
    float bj[4];
    #pragma unroll
    for (int j = 0; j < 4; j++) bj[j] = bias[lane + 32 * j];

    #pragma unroll
    for (int j = 0; j < 4; j++) {
        int   c = lane + 32 * j;
        int   g = (lane >> 4) + 2 * j;
        float s = 0.0f, s2 = 0.0f;
        #pragma unroll
        for (int i = 0; i < 8; i++) {
            float y = f2lo(acc[i][j]) + f2hi(acc[i][j]) + bj[j];
            out_y[(row0 + wid * 8 + i) * CC + c] = y;
            s  += y;
            s2 += y * y;
        }
        atomicAdd(&s_gsum[g], s);
        atomicAdd(&s_gsqs[g], s2);
    }
    __syncthreads();
    if (tid < GROUPS) {
        atomicAdd(&g_sum[layer][b * GROUPS + tid], s_gsum[tid]);
        atomicAdd(&g_sqs[layer][b * GROUPS + tid], s_gsqs[tid]);
    }
}

// ---------------------------------------------------------------------------
// Finalize: out = leaky(GN3(y3))
// ---------------------------------------------------------------------------
__global__ void finalize_kernel(const float* __restrict__ in_y,
                                const float* __restrict__ gamma,
                                const float* __restrict__ beta,
                                float* __restrict__ out) {
    int f  = blockIdx.x * blockDim.x + threadIdx.x;   // float4 index
    int e  = f * 4;
    int c4 = e & (CC - 1);
    int row = e >> 7;
    int b  = row >> 13;
    int g  = c4 >> 4;
    float s  = g_sum[2][b * GROUPS + g];
    float s2 = g_sqs[2][b * GROUPS + g];
    float m  = s * CNT_INV;
    float v  = s2 * CNT_INV - m * m;
    float rs = rsqrtf(v + 1e-5f);
    float4 x = *(const float4*)&in_y[e];
    float4 o;
    o.x = leaky((x.x - m) * rs * gamma[c4 + 0] + beta[c4 + 0]);
    o.y = leaky((x.y - m) * rs * gamma[c4 + 1] + beta[c4 + 1]);
    o.z = leaky((x.z - m) * rs * gamma[c4 + 2] + beta[c4 + 2]);
    o.w = leaky((x.w - m) * rs * gamma[c4 + 3] + beta[c4 + 3]);
    *(float4*)&out[e] = o;
}

// ---------------------------------------------------------------------------
extern "C" void kernel_launch(void* const* d_in, const int* in_sizes, int n_in,
                              void* d_out, int out_size) {
    const float* q_feats  = (const float*)d_in[0];
    const float* s_feats  = (const float*)d_in[1];
    const float* q_points = (const float*)d_in[2];
    const float* s_points = (const float*)d_in[3];
    const int*   nbr_idx  = (const int*)  d_in[4];
    const float* W1 = (const float*)d_in[5];
    const float* b1 = (const float*)d_in[6];
    const float* g1 = (const float*)d_in[7];
    const float* be1 = (const float*)d_in[8];
    const float* W2 = (const float*)d_in[9];
    const float* b2 = (const float*)d_in[10];
    const float* g2 = (const float*)d_in[11];
    const float* be2 = (const float*)d_in[12];
    const float* W3 = (const float*)d_in[13];
    const float* b3 = (const float*)d_in[14];
    const float* g3 = (const float*)d_in[15];
    const float* be3 = (const float*)d_in[16];
    float* out = (float*)d_out;

    float *buf0 = nullptr, *buf1 = nullptr;
    cudaGetSymbolAddress((void**)&buf0, g_buf0);
    cudaGetSymbolAddress((void**)&buf1, g_buf1);

    cudaFuncSetAttribute(layer_kernel<0>, cudaFuncAttributeMaxDynamicSharedMemorySize, SMEM_BYTES);
    cudaFuncSetAttribute(layer_kernel<1>, cudaFuncAttributeMaxDynamicSharedMemorySize, SMEM_BYTES);
    cudaFuncSetAttribute(layer_kernel<2>, cudaFuncAttributeMaxDynamicSharedMemorySize, SMEM_BYTES);

    prep_kernel<<<(3 * CC * CC + THREADS - 1) / THREADS, THREADS>>>(W1, W2, W3);

    const int nblk = NROWS / ROWS_PER_BLK;   // 512
    layer_kernel<0><<<nblk, THREADS, SMEM_BYTES>>>(
        nullptr, nullptr, s_feats, q_points, s_points, nbr_idx,
        b1, nullptr, nullptr, 0, buf0);
    layer_kernel<1><<<nblk, THREADS, SMEM_BYTES>>>(
        buf0, nullptr, nullptr, nullptr, nullptr, nullptr,
        b2, g1, be1, 1, buf1);
    layer_kernel<2><<<nblk, THREADS, SMEM_BYTES>>>(
        buf1, q_feats, nullptr, nullptr, nullptr, nullptr,
        b3, g2, be2, 2, buf0);
    finalize_kernel<<<(NROWS * CC / 4) / THREADS, THREADS>>>(buf0, g3, be3, out);
}